// round 1
// baseline (speedup 1.0000x reference)
#include <cuda_runtime.h>

#define N_ATOMS_C 65536
#define N_BONDS_C 131072
#define N_MOLS_C 2048
#define APM 32
#define ATOM_F_C 133
#define KIN_C 147
#define D_C 300
#define GLOB_F_C 128
#define OUT_C 428

// Scratch (allocation-free rule: __device__ globals). float4 typed for alignment.
__device__ float4 g_inp4 [N_BONDS_C * D_C / 4];
__device__ float4 g_bufA4[N_BONDS_C * D_C / 4];
__device__ float4 g_bufB4[N_BONDS_C * D_C / 4];
__device__ float4 g_msgs4[N_ATOMS_C * D_C / 4];
__device__ float4 g_atoms4[N_ATOMS_C * D_C / 4];

#define g_inp   ((float*)g_inp4)
#define g_bufA  ((float*)g_bufA4)
#define g_bufB  ((float*)g_bufB4)
#define g_msgs  ((float*)g_msgs4)
#define g_atoms ((float*)g_atoms4)

// ---------------------------------------------------------------------------
// Tiled SGEMM: BM=64, BN=64, BK=16, 256 threads, 4x4 microtile per thread.
// MODE 0: C = f_ini @ W_i        -> g_inp = C, g_bufA = relu(C)
// MODE 1: C = g_bufA @ W_h       -> g_bufB = relu(g_inp + C)
// MODE 2: C = [atomF|g_msgs]@W_o -> g_atoms = relu(C + b)
// ---------------------------------------------------------------------------
template <int MODE>
__global__ __launch_bounds__(256)
void gemm_kernel(const float* __restrict__ Aext,
                 const float* __restrict__ W,
                 const float* __restrict__ bias,
                 int M, int K)
{
    __shared__ __align__(16) float As[16][68];   // [k][row], pad for banks
    __shared__ __align__(16) float Bs[16][64];   // [k][col]

    const int tid = threadIdx.x;
    const int tx  = tid & 15;      // col group
    const int ty  = tid >> 4;      // row group
    const int rowBase = blockIdx.x * 64;
    const int colBase = blockIdx.y * 64;

    const float* A1 = (MODE == 1) ? g_bufA : Aext;

    float acc[4][4];
#pragma unroll
    for (int i = 0; i < 4; i++)
#pragma unroll
        for (int j = 0; j < 4; j++) acc[i][j] = 0.f;

    const int ar  = tid >> 2;          // 0..63 : A row in tile
    const int akq = (tid & 3) << 2;    // 0,4,8,12 : A k base
    const int bk  = tid >> 4;          // 0..15 : B k
    const int bn  = (tid & 15) << 2;   // 0..60 : B col base

    for (int k0 = 0; k0 < K; k0 += 16) {
        // ---- load A tile (scalar with bounds; MODE 2 virtual-concat) ----
        {
            const int grow = rowBase + ar;
#pragma unroll
            for (int j = 0; j < 4; j++) {
                const int gk = k0 + akq + j;
                float v = 0.f;
                if (gk < K) {
                    if (MODE == 2) {
                        v = (gk < ATOM_F_C) ? Aext[grow * ATOM_F_C + gk]
                                            : g_msgs[grow * D_C + (gk - ATOM_F_C)];
                    } else {
                        v = A1[grow * K + gk];
                    }
                }
                As[akq + j][ar] = v;
            }
        }
        // ---- load B tile (W is [K x 300] row-major) ----
        {
            const int gk = k0 + bk;
            const float* Wrow = W + gk * D_C;
#pragma unroll
            for (int j = 0; j < 4; j++) {
                const int gn = colBase + bn + j;
                float v = 0.f;
                if (gk < K && gn < D_C) v = Wrow[gn];
                Bs[bk][bn + j] = v;
            }
        }
        __syncthreads();

#pragma unroll
        for (int k = 0; k < 16; k++) {
            const float4 a = *(const float4*)&As[k][ty << 2];
            const float4 b = *(const float4*)&Bs[k][tx << 2];
            const float av[4] = {a.x, a.y, a.z, a.w};
            const float bv[4] = {b.x, b.y, b.z, b.w};
#pragma unroll
            for (int i = 0; i < 4; i++)
#pragma unroll
                for (int j = 0; j < 4; j++)
                    acc[i][j] += av[i] * bv[j];
        }
        __syncthreads();
    }

    // ---- epilogue ----
#pragma unroll
    for (int i = 0; i < 4; i++) {
        const int grow = rowBase + (ty << 2) + i;
#pragma unroll
        for (int j = 0; j < 4; j++) {
            const int gcol = colBase + (tx << 2) + j;
            if (gcol < D_C) {
                const int idx = grow * D_C + gcol;
                const float c = acc[i][j];
                if (MODE == 0) {
                    g_inp[idx]  = c;
                    g_bufA[idx] = fmaxf(c, 0.f);
                } else if (MODE == 1) {
                    g_bufB[idx] = fmaxf(g_inp[idx] + c, 0.f);
                } else {
                    g_atoms[idx] = fmaxf(c + bias[gcol], 0.f);
                }
            }
        }
    }
}

// ---------------------------------------------------------------------------
// 4-way gather-sum over rows of a [*,300] matrix, float4-vectorized.
// phase 0: g_bufA -> g_bufB (m1)   phase 1: g_bufB -> g_bufA (m2)
// phase 2: g_bufB -> g_msgs (atom aggregation)
// ---------------------------------------------------------------------------
__global__ __launch_bounds__(256)
void gather_kernel(int phase, const int* __restrict__ map, int nRows)
{
    const int C4 = D_C / 4;  // 75
    const int idx = blockIdx.x * blockDim.x + threadIdx.x;
    if (idx >= nRows * C4) return;
    const int row = idx / C4;
    const int c   = idx - row * C4;

    const float4* src = (phase == 0) ? g_bufA4 : g_bufB4;
    float4* dst = (phase == 0) ? g_bufB4 : (phase == 1) ? g_bufA4 : g_msgs4;

    const int4 m = *(const int4*)(map + (row << 2));
    const float4 s0 = src[m.x * C4 + c];
    const float4 s1 = src[m.y * C4 + c];
    const float4 s2 = src[m.z * C4 + c];
    const float4 s3 = src[m.w * C4 + c];

    float4 r;
    r.x = (s0.x + s1.x) + (s2.x + s3.x);
    r.y = (s0.y + s1.y) + (s2.y + s3.y);
    r.z = (s0.z + s1.z) + (s2.z + s3.z);
    r.w = (s0.w + s1.w) + (s2.w + s3.w);
    dst[row * C4 + c] = r;
}

// ---------------------------------------------------------------------------
// Per-molecule mean over 32 atoms + global feature concat.
// ---------------------------------------------------------------------------
__global__ __launch_bounds__(448)
void readout_kernel(const float* __restrict__ glob, float* __restrict__ out)
{
    const int mol = blockIdx.x;
    const int c   = threadIdx.x;
    if (c < D_C) {
        const float* base = g_atoms + (size_t)mol * APM * D_C + c;
        float s = 0.f;
#pragma unroll 8
        for (int a = 0; a < APM; a++) s += base[a * D_C];
        out[mol * OUT_C + c] = s * (1.0f / 32.0f);
    } else if (c < OUT_C) {
        out[mol * OUT_C + c] = glob[mol * GLOB_F_C + (c - D_C)];
    }
}

// ---------------------------------------------------------------------------
extern "C" void kernel_launch(void* const* d_in, const int* in_sizes, int n_in,
                              void* d_out, int out_size)
{
    const float* atom_features   = (const float*)d_in[0];  // [65536,133]
    const float* f_ini           = (const float*)d_in[1];  // [131072,147]
    const float* global_features = (const float*)d_in[2];  // [2048,128]
    const float* W_i             = (const float*)d_in[3];  // [147,300]
    const float* W_h             = (const float*)d_in[4];  // [300,300]
    const float* W_o             = (const float*)d_in[5];  // [433,300]
    const float* b_o             = (const float*)d_in[6];  // [300]
    const int*   a2ib            = (const int*)d_in[7];    // [65536,4]
    const int*   mapping         = (const int*)d_in[8];    // [131072,4]
    // d_in[9] atom_to_mol is the fixed arange//32 pattern -> hardcoded.
    float* out = (float*)d_out;

    const dim3 gBonds(N_BONDS_C / 64, 5);
    const dim3 gAtoms(N_ATOMS_C / 64, 5);

    // 1) inp = f_ini @ W_i ; m0 = relu(inp)
    gemm_kernel<0><<<gBonds, 256>>>(f_ini, W_i, nullptr, N_BONDS_C, KIN_C);

    // 2) m1 = gathersum(m0) ; 3) m2 = gathersum(m1)
    const int gtB = N_BONDS_C * (D_C / 4);
    gather_kernel<<<(gtB + 255) / 256, 256>>>(0, mapping, N_BONDS_C);
    gather_kernel<<<(gtB + 255) / 256, 256>>>(1, mapping, N_BONDS_C);

    // 4) h2 = relu(inp + m2 @ W_h)   (iteration-1 hidden state is dead code)
    gemm_kernel<1><<<gBonds, 256>>>(nullptr, W_h, nullptr, N_BONDS_C, D_C);

    // 5) msgs = gathersum over atom_to_incoming_bonds of h2
    const int gtA = N_ATOMS_C * (D_C / 4);
    gather_kernel<<<(gtA + 255) / 256, 256>>>(2, a2ib, N_ATOMS_C);

    // 6) atoms_h = relu([atomF | msgs] @ W_o + b_o)
    gemm_kernel<2><<<gAtoms, 256>>>(atom_features, W_o, b_o, N_ATOMS_C,
                                    ATOM_F_C + D_C);

    // 7) mean readout + global concat
    readout_kernel<<<N_MOLS_C, 448>>>(global_features, out);
}

// round 3
// speedup vs baseline: 2.3286x; 2.3286x over previous
#include <cuda_runtime.h>
#include <cuda_bf16.h>
#include <cstdint>

#define NB 131072
#define NA 65536
#define NM 2048
#define DH 300
#define AF 133
#define K1 147
#define GF 128
#define OUTC 428

#define KP1 160
#define KP2 320
#define KP3 448

typedef __nv_bfloat16 bf16;

// ---------------- device scratch ----------------
__device__ __align__(16) bf16 g_A1[(size_t)NB * 2 * KP1];
__device__ __align__(16) bf16 g_A2[(size_t)NB * 2 * KP2];
__device__ __align__(16) bf16 g_A3[(size_t)NA * 2 * KP3];
__device__ __align__(16) bf16 g_B1[320 * 3 * KP1];
__device__ __align__(16) bf16 g_B2[320 * 3 * KP2];
__device__ __align__(16) bf16 g_B3[320 * 3 * KP3];
__device__ __align__(16) float g_inp[(size_t)NB * DH];
__device__ __align__(16) float g_m1[(size_t)NB * DH];
__device__ __align__(16) float g_h2[(size_t)NB * DH];
__device__ __align__(16) float g_atoms[(size_t)NA * DH];

// ---------------- helpers ----------------
__device__ __forceinline__ uint32_t s2u(const void* p) {
    uint32_t a;
    asm("{ .reg .u64 t; cvta.to.shared.u64 t, %1; cvt.u32.u64 %0, t; }"
        : "=r"(a) : "l"(p));
    return a;
}
__device__ __forceinline__ void cpa16(uint32_t s, const void* g) {
    asm volatile("cp.async.cg.shared.global [%0], [%1], 16;" :: "r"(s), "l"(g));
}
#define CP_COMMIT() asm volatile("cp.async.commit_group;" ::: "memory")
#define CP_WAIT1()  asm volatile("cp.async.wait_group 1;" ::: "memory")

__device__ __forceinline__ void ldmA(uint32_t* r, uint32_t a) {
    asm volatile("ldmatrix.sync.aligned.m8n8.x4.shared.b16 {%0,%1,%2,%3}, [%4];"
                 : "=r"(r[0]), "=r"(r[1]), "=r"(r[2]), "=r"(r[3]) : "r"(a));
}
__device__ __forceinline__ void ldmB(uint32_t* r, uint32_t a) {
    asm volatile("ldmatrix.sync.aligned.m8n8.x2.shared.b16 {%0,%1}, [%2];"
                 : "=r"(r[0]), "=r"(r[1]) : "r"(a));
}
__device__ __forceinline__ void mma16816(float* c, const uint32_t* a, const uint32_t* b) {
    asm volatile(
        "mma.sync.aligned.m16n8k16.row.col.f32.bf16.bf16.f32 "
        "{%0,%1,%2,%3}, {%4,%5,%6,%7}, {%8,%9}, {%0,%1,%2,%3};"
        : "+f"(c[0]), "+f"(c[1]), "+f"(c[2]), "+f"(c[3])
        : "r"(a[0]), "r"(a[1]), "r"(a[2]), "r"(a[3]), "r"(b[0]), "r"(b[1]));
}
__device__ __forceinline__ void split2(float x, bf16& h, bf16& l) {
    h = __float2bfloat16(x);
    l = __float2bfloat16(x - __bfloat162float(h));
}

// ---------------- weight prep: W[K x 300] -> Bt[320 x 3*KP] = [hi|hi|lo] ----------------
template <int MODE>
__global__ void prep_w(const float* __restrict__ W) {
    constexpr int KP = (MODE == 1) ? KP1 : (MODE == 2) ? KP2 : KP3;
    bf16* B = (MODE == 1) ? g_B1 : (MODE == 2) ? g_B2 : g_B3;
    int idx = blockIdx.x * 256 + threadIdx.x;
    if (idx >= 320 * KP) return;
    int n = idx / KP, kp = idx % KP;
    int src;
    if (MODE == 3) src = (kp < 133) ? kp : (kp >= 136 && kp < 436) ? kp - 3 : -1;
    else if (MODE == 1) src = (kp < K1) ? kp : -1;
    else src = (kp < DH) ? kp : -1;
    float v = (n < 300 && src >= 0) ? W[src * 300 + n] : 0.f;
    bf16 h, l;
    split2(v, h, l);
    B[(size_t)n * 3 * KP + kp] = h;
    B[(size_t)n * 3 * KP + KP + kp] = h;
    B[(size_t)n * 3 * KP + 2 * KP + kp] = l;
}

__global__ void conv_a1(const float* __restrict__ F) {
    int idx = blockIdx.x * 256 + threadIdx.x;
    if (idx >= NB * KP1) return;
    int r = idx / KP1, k = idx % KP1;
    float v = (k < K1) ? F[(size_t)r * K1 + k] : 0.f;
    bf16 h, l;
    split2(v, h, l);
    g_A1[(size_t)r * (2 * KP1) + k] = h;
    g_A1[(size_t)r * (2 * KP1) + KP1 + k] = l;
}

__global__ void conv_a3(const float* __restrict__ AFt) {
    int idx = blockIdx.x * 256 + threadIdx.x;
    if (idx >= NA * 448) return;
    int r = idx / 448, k = idx % 448;
    if (k >= 136 && k < 436) return;   // msgs region filled by gather_atom
    float v = (k < 133) ? AFt[(size_t)r * 133 + k] : 0.f;
    bf16 h, l;
    split2(v, h, l);
    g_A3[(size_t)r * 896 + k] = h;
    g_A3[(size_t)r * 896 + 448 + k] = l;
}

// ---------------- gathers ----------------
__global__ void gather_relu(const int* __restrict__ map) {
    int idx = blockIdx.x * 256 + threadIdx.x;
    if (idx >= NB * 75) return;
    int r = idx / 75, c = idx % 75;
    int4 m = ((const int4*)map)[r];
    const float4* S = (const float4*)g_inp;
    float4 a = S[(size_t)m.x * 75 + c];
    float4 b = S[(size_t)m.y * 75 + c];
    float4 cc = S[(size_t)m.z * 75 + c];
    float4 d = S[(size_t)m.w * 75 + c];
    float4 o;
    o.x = fmaxf(a.x, 0.f) + fmaxf(b.x, 0.f) + fmaxf(cc.x, 0.f) + fmaxf(d.x, 0.f);
    o.y = fmaxf(a.y, 0.f) + fmaxf(b.y, 0.f) + fmaxf(cc.y, 0.f) + fmaxf(d.y, 0.f);
    o.z = fmaxf(a.z, 0.f) + fmaxf(b.z, 0.f) + fmaxf(cc.z, 0.f) + fmaxf(d.z, 0.f);
    o.w = fmaxf(a.w, 0.f) + fmaxf(b.w, 0.f) + fmaxf(cc.w, 0.f) + fmaxf(d.w, 0.f);
    ((float4*)g_m1)[(size_t)r * 75 + c] = o;
}

__global__ void gather_split2k(const int* __restrict__ map) {
    int idx = blockIdx.x * 256 + threadIdx.x;
    if (idx >= NB * 80) return;
    int r = idx / 80, c4 = idx % 80;
    int k = c4 * 4;
    union { uint2 u; bf16 b[4]; } H, L;
    H.u = make_uint2(0, 0); L.u = make_uint2(0, 0);
    if (k < 300) {
        int4 m = ((const int4*)map)[r];
        const float4* S = (const float4*)g_m1;
        float4 a = S[(size_t)m.x * 75 + c4];
        float4 b = S[(size_t)m.y * 75 + c4];
        float4 cc = S[(size_t)m.z * 75 + c4];
        float4 d = S[(size_t)m.w * 75 + c4];
        float s[4] = {a.x + b.x + cc.x + d.x, a.y + b.y + cc.y + d.y,
                      a.z + b.z + cc.z + d.z, a.w + b.w + cc.w + d.w};
#pragma unroll
        for (int j = 0; j < 4; j++) split2(s[j], H.b[j], L.b[j]);
    }
    *(uint2*)&g_A2[(size_t)r * 640 + k] = H.u;
    *(uint2*)&g_A2[(size_t)r * 640 + 320 + k] = L.u;
}

__global__ void gather_atom(const int* __restrict__ a2ib) {
    int idx = blockIdx.x * 256 + threadIdx.x;
    if (idx >= NA * 75) return;
    int r = idx / 75, c4 = idx % 75;
    int4 m = ((const int4*)a2ib)[r];
    const float4* S = (const float4*)g_h2;
    float4 a = S[(size_t)m.x * 75 + c4];
    float4 b = S[(size_t)m.y * 75 + c4];
    float4 cc = S[(size_t)m.z * 75 + c4];
    float4 d = S[(size_t)m.w * 75 + c4];
    float s[4] = {a.x + b.x + cc.x + d.x, a.y + b.y + cc.y + d.y,
                  a.z + b.z + cc.z + d.z, a.w + b.w + cc.w + d.w};
    union { uint2 u; bf16 bb[4]; } H, L;
#pragma unroll
    for (int j = 0; j < 4; j++) split2(s[j], H.bb[j], L.bb[j]);
    int k = 136 + 4 * c4;
    *(uint2*)&g_A3[(size_t)r * 896 + k] = H.u;
    *(uint2*)&g_A3[(size_t)r * 896 + 448 + k] = L.u;
}

// ---------------- mma.sync bf16 GEMM ----------------
// BM=128, BN=160, BK=32, 256 thr, warp grid 2(m) x 4(n), warp tile 64x40.
// smem: 3 stages of { As[128][40] , Bs[160][40] } bf16 (pad 8 for ldmatrix).
#define STG_BYTES 23040
#define AS_BYTES  10240

template <int MODE, int KP>
__global__ void __launch_bounds__(256)
mm_hmma(const float* __restrict__ bias) {
    constexpr int KPC = KP / 32;     // chunks per K segment
    constexpr int NCH = 3 * KPC;     // total k-chunks
    constexpr int KA = 2 * KP;       // A row length (bf16)
    constexpr int KB = 3 * KP;       // B row length (bf16)
    const bf16* __restrict__ A = (MODE == 1) ? g_A1 : (MODE == 2) ? g_A2 : g_A3;
    const bf16* __restrict__ Bt = (MODE == 1) ? g_B1 : (MODE == 2) ? g_B2 : g_B3;
    float* __restrict__ OUTp = (MODE == 1) ? g_inp : (MODE == 2) ? g_h2 : g_atoms;

    extern __shared__ __align__(16) char smem[];
    const uint32_t sb = s2u(smem);
    const int tid = threadIdx.x, w = tid >> 5, lane = tid & 31;
    const int rowBase = blockIdx.x * 128;
    const int colBase = blockIdx.y * 160;
    const int wr = w & 1, wc = w >> 1;           // warp 64x40 tile position

    float acc[4][5][4];
#pragma unroll
    for (int i = 0; i < 4; i++)
#pragma unroll
        for (int j = 0; j < 5; j++)
#pragma unroll
            for (int q = 0; q < 4; q++) acc[i][j][q] = 0.f;

    // per-thread load coords
    const int la_row = tid >> 2, la_seg = tid & 3;             // A: 512 xfers, 2/thr

    auto load_chunk = [&](int c, int st) {
        const int ck = (c < 2 * KPC) ? c : c - 2 * KPC;
        const size_t gaoff = (size_t)(rowBase + la_row) * KA + ck * 32 + la_seg * 8;
        uint32_t sA = sb + st * STG_BYTES + la_row * 80 + la_seg * 16;
        cpa16(sA, A + gaoff);
        cpa16(sA + 64 * 80, A + gaoff + (size_t)64 * KA);
        // B: 640 xfers
        const int kb = c * 32;
#pragma unroll
        for (int it = 0; it < 3; it++) {
            int t = tid + it * 256;
            if (t < 640) {
                int brow = t >> 2, seg = t & 3;
                cpa16(sb + st * STG_BYTES + AS_BYTES + brow * 80 + seg * 16,
                      Bt + (size_t)(colBase + brow) * KB + kb + seg * 8);
            }
        }
    };

    load_chunk(0, 0); CP_COMMIT();
    load_chunk(1, 1); CP_COMMIT();

    // ldmatrix address bases (per-thread invariants)
    const uint32_t aRow = (wr * 64 + (lane & 15)) * 80 + (lane >> 4) * 16;
    const uint32_t bRow = AS_BYTES + (wc * 40 + (lane & 7)) * 80 + (((lane & 15) >> 3)) * 16;

    for (int c = 0; c < NCH; c++) {
        CP_WAIT1();
        __syncthreads();
        if (c + 2 < NCH) load_chunk(c + 2, (c + 2) % 3);
        CP_COMMIT();

        const uint32_t stB = sb + (c % 3) * STG_BYTES;
#pragma unroll
        for (int kh = 0; kh < 2; kh++) {     // two k16 halves of the 32-chunk
            uint32_t af[4][4], bf[5][2];
#pragma unroll
            for (int mt = 0; mt < 4; mt++)
                ldmA(af[mt], stB + aRow + mt * 16 * 80 + kh * 32);
#pragma unroll
            for (int nt = 0; nt < 5; nt++)
                ldmB(bf[nt], stB + bRow + nt * 8 * 80 + kh * 32);
#pragma unroll
            for (int mt = 0; mt < 4; mt++)
#pragma unroll
                for (int nt = 0; nt < 5; nt++)
                    mma16816(acc[mt][nt], af[mt], bf[nt]);
        }
    }

    // ---- epilogue: direct float2 stores from C fragments ----
    const int crow = lane >> 2;
    const int ccol0 = (lane & 3) * 2;
#pragma unroll
    for (int mt = 0; mt < 4; mt++) {
#pragma unroll
        for (int nt = 0; nt < 5; nt++) {
            const int col = colBase + wc * 40 + nt * 8 + ccol0;
            if (col >= DH) continue;
#pragma unroll
            for (int half = 0; half < 2; half++) {
                const int grow = rowBase + wr * 64 + mt * 16 + crow + half * 8;
                const size_t o = (size_t)grow * DH + col;
                float v0 = acc[mt][nt][half * 2];
                float v1 = acc[mt][nt][half * 2 + 1];
                if (MODE == 2) {
                    float2 p = *(const float2*)&g_inp[o];
                    v0 = fmaxf(p.x + v0, 0.f);
                    v1 = fmaxf(p.y + v1, 0.f);
                } else if (MODE == 3) {
                    float2 bb = *(const float2*)&bias[col];
                    v0 = fmaxf(v0 + bb.x, 0.f);
                    v1 = fmaxf(v1 + bb.y, 0.f);
                }
                float2 r; r.x = v0; r.y = v1;
                *(float2*)&OUTp[o] = r;
            }
        }
    }
}

// ---------------- readout ----------------
__global__ void __launch_bounds__(448)
readout_kernel(const float* __restrict__ glob, float* __restrict__ out) {
    const int mol = blockIdx.x;
    const int c = threadIdx.x;
    if (c < DH) {
        const float* base = g_atoms + (size_t)mol * 32 * DH + c;
        float s = 0.f;
#pragma unroll 8
        for (int a = 0; a < 32; a++) s += base[a * DH];
        out[(size_t)mol * OUTC + c] = s * (1.0f / 32.0f);
    } else if (c < OUTC) {
        out[(size_t)mol * OUTC + c] = glob[(size_t)mol * GF + (c - DH)];
    }
}

// ---------------- launch ----------------
extern "C" void kernel_launch(void* const* d_in, const int* in_sizes, int n_in,
                              void* d_out, int out_size) {
    const float* atom_features   = (const float*)d_in[0];
    const float* f_ini           = (const float*)d_in[1];
    const float* global_features = (const float*)d_in[2];
    const float* W_i             = (const float*)d_in[3];
    const float* W_h             = (const float*)d_in[4];
    const float* W_o             = (const float*)d_in[5];
    const float* b_o             = (const float*)d_in[6];
    const int*   a2ib            = (const int*)d_in[7];
    const int*   mapping         = (const int*)d_in[8];
    float* out = (float*)d_out;

    const int smemSz = 3 * STG_BYTES;   // 69120
    static bool cfg = false;
    if (!cfg) {
        cudaFuncSetAttribute(mm_hmma<1, KP1>, cudaFuncAttributeMaxDynamicSharedMemorySize, smemSz);
        cudaFuncSetAttribute(mm_hmma<2, KP2>, cudaFuncAttributeMaxDynamicSharedMemorySize, smemSz);
        cudaFuncSetAttribute(mm_hmma<3, KP3>, cudaFuncAttributeMaxDynamicSharedMemorySize, smemSz);
        cfg = true;
    }

    prep_w<1><<<(320 * KP1 + 255) / 256, 256>>>(W_i);
    prep_w<2><<<(320 * KP2 + 255) / 256, 256>>>(W_h);
    prep_w<3><<<(320 * KP3 + 255) / 256, 256>>>(W_o);
    conv_a1<<<(NB * KP1 + 255) / 256, 256>>>(f_ini);
    conv_a3<<<(NA * 448 + 255) / 256, 256>>>(atom_features);

    // 1) inp = f_ini @ W_i
    mm_hmma<1, KP1><<<dim3(NB / 128, 2), 256, smemSz>>>(nullptr);
    // 2) m1 = sum relu(inp[mapping])
    gather_relu<<<(NB * 75 + 255) / 256, 256>>>(mapping);
    // 3) m2 = sum m1[mapping] -> A2' split
    gather_split2k<<<(NB * 80 + 255) / 256, 256>>>(mapping);
    // 4) h2 = relu(inp + m2 @ W_h)
    mm_hmma<2, KP2><<<dim3(NB / 128, 2), 256, smemSz>>>(nullptr);
    // 5) msgs = sum h2[a2ib] -> A3' msgs part
    gather_atom<<<(NA * 75 + 255) / 256, 256>>>(a2ib);
    // 6) atoms_h = relu([atomF|msgs] @ W_o + b_o)
    mm_hmma<3, KP3><<<dim3(NA / 128, 2), 256, smemSz>>>(b_o);
    // 7) readout
    readout_kernel<<<NM, 448>>>(global_features, out);
}

// round 4
// speedup vs baseline: 2.6366x; 1.1323x over previous
#include <cuda_runtime.h>
#include <cstdint>

#define NB 131072
#define NA 65536
#define NM 2048
#define DH 300
#define AF 133
#define K1 147
#define GF 128
#define OUTC 428

#define KP1 160
#define KP2 320
#define KP3 448

// ---------------- device scratch ----------------
__device__ __align__(16) float g_Af1[(size_t)NB * KP1];   // padded f_ini (tf32)
__device__ __align__(16) float g_m2 [(size_t)NB * KP2];   // gather2 out (tf32)
__device__ __align__(16) float g_Af3[(size_t)NA * KP3];   // [atomF|pad|msgs|pad] (tf32)
__device__ __align__(16) float g_W1[320 * KP1];
__device__ __align__(16) float g_W2[320 * KP2];
__device__ __align__(16) float g_W3[320 * KP3];
__device__ __align__(16) float g_inp[(size_t)NB * DH];
__device__ __align__(16) float g_m1 [(size_t)NB * DH];
__device__ __align__(16) float g_h2 [(size_t)NB * DH];

// ---------------- helpers ----------------
__device__ __forceinline__ uint32_t s2u(const void* p) {
    uint32_t a;
    asm("{ .reg .u64 t; cvta.to.shared.u64 t, %1; cvt.u32.u64 %0, t; }"
        : "=r"(a) : "l"(p));
    return a;
}
__device__ __forceinline__ void cpa16(uint32_t s, const void* g) {
    asm volatile("cp.async.cg.shared.global [%0], [%1], 16;" :: "r"(s), "l"(g));
}
#define CP_COMMIT() asm volatile("cp.async.commit_group;" ::: "memory")
#define CP_WAIT1()  asm volatile("cp.async.wait_group 1;" ::: "memory")

__device__ __forceinline__ float rtf32(float x) {
    uint32_t u;
    asm("cvt.rna.tf32.f32 %0, %1;" : "=r"(u) : "f"(x));
    return __uint_as_float(u);
}
__device__ __forceinline__ void mma_tf32(float* c, const float* a, const float* b) {
    asm volatile(
        "mma.sync.aligned.m16n8k8.row.col.f32.tf32.tf32.f32 "
        "{%0,%1,%2,%3}, {%4,%5,%6,%7}, {%8,%9}, {%0,%1,%2,%3};"
        : "+f"(c[0]), "+f"(c[1]), "+f"(c[2]), "+f"(c[3])
        : "r"(__float_as_uint(a[0])), "r"(__float_as_uint(a[1])),
          "r"(__float_as_uint(a[2])), "r"(__float_as_uint(a[3])),
          "r"(__float_as_uint(b[0])), "r"(__float_as_uint(b[1])));
}

// ---------------- weight prep: W[K x 300] -> Wt[320 x KP] (n-major, tf32) ----------------
template <int MODE>
__global__ void prep_w(const float* __restrict__ W) {
    constexpr int KP = (MODE == 1) ? KP1 : (MODE == 2) ? KP2 : KP3;
    float* B = (MODE == 1) ? g_W1 : (MODE == 2) ? g_W2 : g_W3;
    int idx = blockIdx.x * 256 + threadIdx.x;
    if (idx >= 320 * KP) return;
    int n = idx / KP, k = idx % KP;
    int src;
    if (MODE == 3) src = (k < 133) ? k : (k >= 136 && k < 436) ? k - 3 : -1;
    else if (MODE == 1) src = (k < K1) ? k : -1;
    else src = (k < DH) ? k : -1;
    float v = (n < 300 && src >= 0) ? W[src * 300 + n] : 0.f;
    B[(size_t)n * KP + k] = rtf32(v);
}

// ---------------- pad f_ini -> [NB x 160] tf32 ----------------
__global__ void pad1(const float* __restrict__ F) {
    int idx = blockIdx.x * 256 + threadIdx.x;
    if (idx >= NB * 40) return;
    int r = idx / 40, k = (idx % 40) * 4;
    float4 v;
    v.x = (k + 0 < K1) ? rtf32(F[(size_t)r * K1 + k + 0]) : 0.f;
    v.y = (k + 1 < K1) ? rtf32(F[(size_t)r * K1 + k + 1]) : 0.f;
    v.z = (k + 2 < K1) ? rtf32(F[(size_t)r * K1 + k + 2]) : 0.f;
    v.w = (k + 3 < K1) ? rtf32(F[(size_t)r * K1 + k + 3]) : 0.f;
    *(float4*)&g_Af1[(size_t)r * KP1 + k] = v;
}

// ---------------- atom_features -> cols 0..132 of g_Af3 ----------------
__global__ void pad3(const float* __restrict__ AFt) {
    int idx = blockIdx.x * 256 + threadIdx.x;
    if (idx >= NA * 136) return;
    int r = idx / 136, k = idx % 136;
    float v = (k < AF) ? rtf32(AFt[(size_t)r * AF + k]) : 0.f;
    g_Af3[(size_t)r * KP3 + k] = v;
}

// ---------------- gathers ----------------
__global__ void gather_relu(const int* __restrict__ map) {
    int idx = blockIdx.x * 256 + threadIdx.x;
    if (idx >= NB * 75) return;
    int r = idx / 75, c = idx % 75;
    int4 m = ((const int4*)map)[r];
    const float4* S = (const float4*)g_inp;
    float4 a = S[(size_t)m.x * 75 + c];
    float4 b = S[(size_t)m.y * 75 + c];
    float4 cc = S[(size_t)m.z * 75 + c];
    float4 d = S[(size_t)m.w * 75 + c];
    float4 o;
    o.x = fmaxf(a.x, 0.f) + fmaxf(b.x, 0.f) + fmaxf(cc.x, 0.f) + fmaxf(d.x, 0.f);
    o.y = fmaxf(a.y, 0.f) + fmaxf(b.y, 0.f) + fmaxf(cc.y, 0.f) + fmaxf(d.y, 0.f);
    o.z = fmaxf(a.z, 0.f) + fmaxf(b.z, 0.f) + fmaxf(cc.z, 0.f) + fmaxf(d.z, 0.f);
    o.w = fmaxf(a.w, 0.f) + fmaxf(b.w, 0.f) + fmaxf(cc.w, 0.f) + fmaxf(d.w, 0.f);
    ((float4*)g_m1)[(size_t)r * 75 + c] = o;
}

__global__ void gather2(const int* __restrict__ map) {
    int idx = blockIdx.x * 256 + threadIdx.x;
    if (idx >= NB * 75) return;
    int r = idx / 75, c = idx % 75;
    int4 m = ((const int4*)map)[r];
    const float4* S = (const float4*)g_m1;
    float4 a = S[(size_t)m.x * 75 + c];
    float4 b = S[(size_t)m.y * 75 + c];
    float4 cc = S[(size_t)m.z * 75 + c];
    float4 d = S[(size_t)m.w * 75 + c];
    float4 o;
    o.x = rtf32(a.x + b.x + cc.x + d.x);
    o.y = rtf32(a.y + b.y + cc.y + d.y);
    o.z = rtf32(a.z + b.z + cc.z + d.z);
    o.w = rtf32(a.w + b.w + cc.w + d.w);
    *(float4*)&g_m2[(size_t)r * KP2 + c * 4] = o;
}

__global__ void gather_atom(const int* __restrict__ a2ib) {
    int idx = blockIdx.x * 256 + threadIdx.x;
    if (idx >= NA * 75) return;
    int r = idx / 75, c = idx % 75;
    int4 m = ((const int4*)a2ib)[r];
    const float4* S = (const float4*)g_h2;
    float4 a = S[(size_t)m.x * 75 + c];
    float4 b = S[(size_t)m.y * 75 + c];
    float4 cc = S[(size_t)m.z * 75 + c];
    float4 d = S[(size_t)m.w * 75 + c];
    float4 o;
    o.x = rtf32(a.x + b.x + cc.x + d.x);
    o.y = rtf32(a.y + b.y + cc.y + d.y);
    o.z = rtf32(a.z + b.z + cc.z + d.z);
    o.w = rtf32(a.w + b.w + cc.w + d.w);
    *(float4*)&g_Af3[(size_t)r * KP3 + 136 + c * 4] = o;
}

// ---------------- TF32 GEMM: BM=128, BN=160, BK=32, 256 thr, 3-stage cp.async ----------------
// smem stage: A 128x(32+4)f = 18432 B, B 160x(32+4)f = 23040 B
#define STG  41472
#define BOFF 18432

template <int MODE, int KP>
__global__ void __launch_bounds__(256)
mm_tf32(const float* __restrict__ bias, float* __restrict__ dOut) {
    constexpr int NCH = KP / 32;
    const float* __restrict__ A  = (MODE == 1) ? g_Af1 : (MODE == 2) ? g_m2 : g_Af3;
    const float* __restrict__ Wt = (MODE == 1) ? g_W1 : (MODE == 2) ? g_W2 : g_W3;

    extern __shared__ __align__(16) char smem[];
    const uint32_t sb = s2u(smem);
    const int tid = threadIdx.x, w = tid >> 5, lane = tid & 31;
    const int wr = w & 1, wc = w >> 1;       // warp tile 64x40
    const int rowBase = blockIdx.y * 128;
    const int colBase = blockIdx.x * 160;

    float acc[4][5][4];
#pragma unroll
    for (int i = 0; i < 4; i++)
#pragma unroll
        for (int j = 0; j < 5; j++)
#pragma unroll
            for (int q = 0; q < 4; q++) acc[i][j][q] = 0.f;

    const int lrow = tid >> 3, lseg = tid & 7;

    auto load_chunk = [&](int c, int st) {
        // A: 128 rows x 8 segs = 1024 xfers
#pragma unroll
        for (int it = 0; it < 4; it++) {
            int row = lrow + it * 32;
            cpa16(sb + st * STG + row * 144 + lseg * 16,
                  A + (size_t)(rowBase + row) * KP + c * 32 + lseg * 4);
        }
        // B: 160 rows x 8 segs = 1280 xfers
#pragma unroll
        for (int it = 0; it < 5; it++) {
            int row = lrow + it * 32;
            cpa16(sb + st * STG + BOFF + row * 144 + lseg * 16,
                  Wt + (size_t)(colBase + row) * KP + c * 32 + lseg * 4);
        }
    };

    load_chunk(0, 0); CP_COMMIT();
    load_chunk(1, 1); CP_COMMIT();

    const uint32_t aBase = (wr * 64 + (lane >> 2)) * 144 + (lane & 3) * 4;
    const uint32_t bBase = BOFF + (wc * 40 + (lane >> 2)) * 144 + (lane & 3) * 4;

    for (int c = 0; c < NCH; c++) {
        CP_WAIT1();
        __syncthreads();
        if (c + 2 < NCH) load_chunk(c + 2, (c + 2) % 3);
        CP_COMMIT();

        const char* stp = smem + (c % 3) * STG;
#pragma unroll
        for (int k8 = 0; k8 < 4; k8++) {
            float af[4][4], bfr[5][2];
#pragma unroll
            for (int mt = 0; mt < 4; mt++) {
                const char* p = stp + aBase + mt * (16 * 144) + k8 * 32;
                af[mt][0] = *(const float*)p;
                af[mt][1] = *(const float*)(p + 8 * 144);
                af[mt][2] = *(const float*)(p + 16);
                af[mt][3] = *(const float*)(p + 8 * 144 + 16);
            }
#pragma unroll
            for (int nt = 0; nt < 5; nt++) {
                const char* p = stp + bBase + nt * (8 * 144) + k8 * 32;
                bfr[nt][0] = *(const float*)p;
                bfr[nt][1] = *(const float*)(p + 16);
            }
#pragma unroll
            for (int mt = 0; mt < 4; mt++)
#pragma unroll
                for (int nt = 0; nt < 5; nt++)
                    mma_tf32(acc[mt][nt], af[mt], bfr[nt]);
        }
    }

    if (MODE == 3) {
        // fused per-molecule mean readout: 128 rows = 4 molecules
        const int molBase = blockIdx.y * 4 + wr * 2;
#pragma unroll
        for (int mtb = 0; mtb < 4; mtb += 2) {
#pragma unroll
            for (int nt = 0; nt < 5; nt++) {
                const int col2 = colBase + wc * 40 + nt * 8 + (lane & 3) * 2;
                float b0 = 0.f, b1 = 0.f;
                if (col2 < DH) { b0 = bias[col2]; b1 = bias[col2 + 1]; }
                float s0 = 0.f, s1 = 0.f;
#pragma unroll
                for (int p = 0; p < 2; p++) {
#pragma unroll
                    for (int h = 0; h < 2; h++) {
                        s0 += fmaxf(acc[mtb + p][nt][h * 2]     + b0, 0.f);
                        s1 += fmaxf(acc[mtb + p][nt][h * 2 + 1] + b1, 0.f);
                    }
                }
#pragma unroll
                for (int off = 16; off >= 4; off >>= 1) {
                    s0 += __shfl_down_sync(0xFFFFFFFFu, s0, off);
                    s1 += __shfl_down_sync(0xFFFFFFFFu, s1, off);
                }
                if (lane < 4) {
                    const int colw = colBase + wc * 40 + nt * 8 + lane * 2;
                    if (colw < DH) {
                        const int mol = molBase + (mtb >> 1);
                        float2 v;
                        v.x = s0 * 0.03125f;
                        v.y = s1 * 0.03125f;
                        *(float2*)&dOut[(size_t)mol * OUTC + colw] = v;
                    }
                }
            }
        }
    } else {
        float* __restrict__ OUTp = (MODE == 1) ? g_inp : g_h2;
        const int crow = lane >> 2, cc0 = (lane & 3) * 2;
#pragma unroll
        for (int mt = 0; mt < 4; mt++) {
#pragma unroll
            for (int nt = 0; nt < 5; nt++) {
                const int col = colBase + wc * 40 + nt * 8 + cc0;
                if (col >= DH) continue;
#pragma unroll
                for (int half = 0; half < 2; half++) {
                    const int grow = rowBase + wr * 64 + mt * 16 + crow + half * 8;
                    const size_t o = (size_t)grow * DH + col;
                    float v0 = acc[mt][nt][half * 2];
                    float v1 = acc[mt][nt][half * 2 + 1];
                    if (MODE == 2) {
                        float2 pv = *(const float2*)&g_inp[o];
                        v0 = fmaxf(pv.x + v0, 0.f);
                        v1 = fmaxf(pv.y + v1, 0.f);
                    }
                    float2 r; r.x = v0; r.y = v1;
                    *(float2*)&OUTp[o] = r;
                }
            }
        }
    }
}

// ---------------- global-feature concat ----------------
__global__ void glob_copy(const float* __restrict__ g, float* __restrict__ out) {
    int idx = blockIdx.x * 256 + threadIdx.x;
    if (idx >= NM * 32) return;
    int mol = idx >> 5, j4 = idx & 31;
    float4 v = ((const float4*)g)[mol * 32 + j4];
    *(float4*)&out[(size_t)mol * OUTC + 300 + 4 * j4] = v;
}

// ---------------- launch ----------------
extern "C" void kernel_launch(void* const* d_in, const int* in_sizes, int n_in,
                              void* d_out, int out_size) {
    const float* atom_features   = (const float*)d_in[0];
    const float* f_ini           = (const float*)d_in[1];
    const float* global_features = (const float*)d_in[2];
    const float* W_i             = (const float*)d_in[3];
    const float* W_h             = (const float*)d_in[4];
    const float* W_o             = (const float*)d_in[5];
    const float* b_o             = (const float*)d_in[6];
    const int*   a2ib            = (const int*)d_in[7];
    const int*   mapping         = (const int*)d_in[8];
    float* out = (float*)d_out;

    const int smemSz = 3 * STG;   // 124416
    static bool cfg = false;
    if (!cfg) {
        cudaFuncSetAttribute(mm_tf32<1, KP1>, cudaFuncAttributeMaxDynamicSharedMemorySize, smemSz);
        cudaFuncSetAttribute(mm_tf32<2, KP2>, cudaFuncAttributeMaxDynamicSharedMemorySize, smemSz);
        cudaFuncSetAttribute(mm_tf32<3, KP3>, cudaFuncAttributeMaxDynamicSharedMemorySize, smemSz);
        cfg = true;
    }

    glob_copy<<<(NM * 32 + 255) / 256, 256>>>(global_features, out);
    prep_w<1><<<(320 * KP1 + 255) / 256, 256>>>(W_i);
    prep_w<2><<<(320 * KP2 + 255) / 256, 256>>>(W_h);
    prep_w<3><<<(320 * KP3 + 255) / 256, 256>>>(W_o);
    pad1<<<(NB * 40 + 255) / 256, 256>>>(f_ini);
    pad3<<<(NA * 136 + 255) / 256, 256>>>(atom_features);

    // 1) inp = f_ini @ W_i
    mm_tf32<1, KP1><<<dim3(2, NB / 128), 256, smemSz>>>(nullptr, nullptr);
    // 2) m1 = sum relu(inp[mapping])
    gather_relu<<<(NB * 75 + 255) / 256, 256>>>(mapping);
    // 3) m2 = sum m1[mapping]  (tf32-rounded into padded A2)
    gather2<<<(NB * 75 + 255) / 256, 256>>>(mapping);
    // 4) h2 = relu(inp + m2 @ W_h)
    mm_tf32<2, KP2><<<dim3(2, NB / 128), 256, smemSz>>>(nullptr, nullptr);
    // 5) msgs = sum h2[a2ib]  (tf32-rounded into A3 concat region)
    gather_atom<<<(NA * 75 + 255) / 256, 256>>>(a2ib);
    // 6) atoms_h = relu([atomF|msgs] @ W_o + b_o) + fused mean readout
    mm_tf32<3, KP3><<<dim3(2, NA / 128), 256, smemSz>>>(b_o, out);
}